// round 10
// baseline (speedup 1.0000x reference)
#include <cuda_runtime.h>
#include <cuda_fp16.h>
#include <cstdint>

#define NN 100000
#define EE 1600000
#define DD 128
#define LL 5
#define GG 128
#define TT 10
#define NBOND 4
#define BN_EPS 1e-5f
#define NB_AGG 1184         // agg grid blocks (8/SM)
#define NCHUNK 98           // ceil(NN/1024)

// ---------------- scratch (device globals) -----------------------------------
__device__ float   g_hx [NN * DD];    // fp32 linear output (self term)
__device__ __half2 g_hxh[NN * 64];    // fp16 copy for edge gather
__device__ float   g_h2 [NN * DD];
__device__ float   g_deg [NN];
__device__ float   g_dinv[NN];
__device__ int     g_indeg[NN];
__device__ int     g_cur  [NN];
__device__ int     g_rowptr[NN + 1];
__device__ int     g_blocksum[NCHUNK];
__device__ int     g_blockoff[NCHUNK];
__device__ int     g_epack[EE];       // row | attr<<17, CSR order by dest
__device__ float   g_enorm[EE];
__device__ float   g_partS [NB_AGG * DD];
__device__ float   g_partSS[NB_AGG * DD];
__device__ float   g_bnp[2 * DD];     // scale / shift
__device__ float   g_pool[GG * DD];
__device__ float   g_cnt [GG];

// ---------------- prolog ------------------------------------------------------
__global__ void k_init() {
    int i = blockIdx.x * blockDim.x + threadIdx.x;
    if (i < NN) { g_deg[i] = 1.0f; g_indeg[i] = 0; g_cur[i] = 0; }
    if (i < GG * DD) g_pool[i] = 0.f;
    if (i < GG) g_cnt[i] = 0.f;
}
__global__ void k_count(const int* __restrict__ row, const int* __restrict__ col) {
    int e = blockIdx.x * blockDim.x + threadIdx.x;
    if (e < EE) {
        atomicAdd(&g_deg[row[e]], 1.0f);
        atomicAdd(&g_indeg[col[e]], 1);
    }
}
__global__ void k_dinv() {
    int i = blockIdx.x * blockDim.x + threadIdx.x;
    if (i < NN) g_dinv[i] = rsqrtf(g_deg[i]);
}
__global__ void k_scan1() {
    __shared__ int sm[1024];
    int tid = threadIdx.x;
    int i = blockIdx.x * 1024 + tid;
    int v = (i < NN) ? g_indeg[i] : 0;
    sm[tid] = v;
    __syncthreads();
    for (int off = 1; off < 1024; off <<= 1) {
        int t = (tid >= off) ? sm[tid - off] : 0;
        __syncthreads();
        sm[tid] += t;
        __syncthreads();
    }
    if (i < NN) g_rowptr[i] = sm[tid] - v;
    if (tid == 1023) g_blocksum[blockIdx.x] = sm[1023];
}
__global__ void k_scan2() {
    if (threadIdx.x == 0) {
        int run = 0;
        for (int bk = 0; bk < NCHUNK; bk++) { g_blockoff[bk] = run; run += g_blocksum[bk]; }
    }
}
__global__ void k_scan3() {
    int i = blockIdx.x * blockDim.x + threadIdx.x;
    if (i < NN) g_rowptr[i] += g_blockoff[i >> 10];
    if (i == 0) g_rowptr[NN] = EE;
}
__global__ void k_scatter(const int* __restrict__ row, const int* __restrict__ col,
                          const int* __restrict__ ea) {
    int e = blockIdx.x * blockDim.x + threadIdx.x;
    if (e >= EE) return;
    int r = row[e], c = col[e], a = ea[e];
    float nv = g_dinv[r] * g_dinv[c];
    int pos = g_rowptr[c] + atomicAdd(&g_cur[c], 1);
    g_epack[pos] = r | (a << 17);
    g_enorm[pos] = nv;
}

// ---------------- linear: hx = act(h) @ W + b  (4 rows/warp, R4-proven) -------
__global__ void k_linear(const float* __restrict__ h, const float* __restrict__ W,
                         const float* __restrict__ b, int use_bn) {
    int lane = threadIdx.x & 31;
    int gw   = (blockIdx.x * blockDim.x + threadIdx.x) >> 5;
    int r0   = gw * 4;
    if (r0 >= NN) return;
    const float4* h4 = use_bn ? (const float4*)g_h2 : (const float4*)h;
    const float4* W4 = (const float4*)W;
    float4 bv = ((const float4*)b)[lane];
    float4 sc, sh;
    if (use_bn) {
        sc = ((const float4*)g_bnp)[lane];
        sh = ((const float4*)g_bnp)[32 + lane];
    }
    float ha[4][4];
    float4 acc[4];
#pragma unroll
    for (int i = 0; i < 4; i++) {
        float4 t = h4[(size_t)(r0 + i) * 32 + lane];
        if (use_bn) {
            t.x = fmaxf(t.x * sc.x + sh.x, 0.f);
            t.y = fmaxf(t.y * sc.y + sh.y, 0.f);
            t.z = fmaxf(t.z * sc.z + sh.z, 0.f);
            t.w = fmaxf(t.w * sc.w + sh.w, 0.f);
        }
        ha[i][0] = t.x; ha[i][1] = t.y; ha[i][2] = t.z; ha[i][3] = t.w;
        acc[i] = bv;
    }
#pragma unroll 16
    for (int k = 0; k < 128; k++) {
        float4 w = W4[k * 32 + lane];
#pragma unroll
        for (int i = 0; i < 4; i++) {
            float hk = __shfl_sync(0xffffffffu, ha[i][k & 3], k >> 2);
            acc[i].x += hk * w.x; acc[i].y += hk * w.y;
            acc[i].z += hk * w.z; acc[i].w += hk * w.w;
        }
    }
#pragma unroll
    for (int i = 0; i < 4; i++) {
        ((float4*)g_hx)[(size_t)(r0 + i) * 32 + lane] = acc[i];
        __half2 p0 = __floats2half2_rn(acc[i].x, acc[i].y);
        __half2 p1 = __floats2half2_rn(acc[i].z, acc[i].w);
        uint2 pp;
        pp.x = *reinterpret_cast<unsigned*>(&p0);
        pp.y = *reinterpret_cast<unsigned*>(&p1);
        ((uint2*)g_hxh)[(size_t)(r0 + i) * 32 + lane] = pp;
    }
}

// ---------------- fused aggregation: fp16 gather + self + BN partial stats ----
__global__ void __launch_bounds__(256) k_agg(const float* __restrict__ bond,
                                             const float* __restrict__ root) {
    __shared__ float   sS [8][DD];
    __shared__ float   sSS[8][DD];
    __shared__ __half2 sbond[NBOND][64];
    int lane = threadIdx.x & 31;
    int wid  = threadIdx.x >> 5;
    // stage bond table as half2 (256 threads cover 4*64 entries)
    {
        int a = threadIdx.x >> 6, j = threadIdx.x & 63;
        sbond[a][j] = __floats2half2_rn(bond[a * DD + 2 * j], bond[a * DD + 2 * j + 1]);
    }
    __syncthreads();

    const uint2*  hxh = (const uint2*)g_hxh;
    const float4* hx4 = (const float4*)g_hx;
    float4 rt = ((const float4*)root)[lane];
    const __half2 z2 = __floats2half2_rn(0.f, 0.f);
    float4 s4  = {0, 0, 0, 0};
    float4 ss4 = {0, 0, 0, 0};

    for (int c = blockIdx.x * 8 + wid; c < NN; c += NB_AGG * 8) {
        float4 acc = {0, 0, 0, 0};
        int e0 = g_rowptr[c], e1 = g_rowptr[c + 1];
        if (e0 < e1) {
            int p  = g_epack[e0];
            float nv = g_enorm[e0];
            for (int e = e0; e < e1; e++) {
                int pn = 0; float nvn = 0.f;
                if (e + 1 < e1) { pn = g_epack[e + 1]; nvn = g_enorm[e + 1]; }
                int r = p & 0x1FFFF;
                int a = p >> 17;
                uint2 hv = hxh[(size_t)r * 32 + lane];
                __half2 h0 = *reinterpret_cast<__half2*>(&hv.x);
                __half2 h1 = *reinterpret_cast<__half2*>(&hv.y);
                __half2 m0 = __hmax2(__hadd2(h0, sbond[a][lane * 2]),     z2);
                __half2 m1 = __hmax2(__hadd2(h1, sbond[a][lane * 2 + 1]), z2);
                float2 f0 = __half22float2(m0);
                float2 f1 = __half22float2(m1);
                acc.x += nv * f0.x; acc.y += nv * f0.y;
                acc.z += nv * f1.x; acc.w += nv * f1.y;
                p = pn; nv = nvn;
            }
        }
        // self/root term (fp32)
        float4 hv = hx4[(size_t)c * 32 + lane];
        float inv = 1.0f / g_deg[c];
        acc.x += fmaxf(hv.x + rt.x, 0.f) * inv;
        acc.y += fmaxf(hv.y + rt.y, 0.f) * inv;
        acc.z += fmaxf(hv.z + rt.z, 0.f) * inv;
        acc.w += fmaxf(hv.w + rt.w, 0.f) * inv;
        ((float4*)g_h2)[(size_t)c * 32 + lane] = acc;
        s4.x += acc.x; s4.y += acc.y; s4.z += acc.z; s4.w += acc.w;
        ss4.x += acc.x * acc.x; ss4.y += acc.y * acc.y;
        ss4.z += acc.z * acc.z; ss4.w += acc.w * acc.w;
    }
    sS [wid][lane * 4 + 0] = s4.x;  sS [wid][lane * 4 + 1] = s4.y;
    sS [wid][lane * 4 + 2] = s4.z;  sS [wid][lane * 4 + 3] = s4.w;
    sSS[wid][lane * 4 + 0] = ss4.x; sSS[wid][lane * 4 + 1] = ss4.y;
    sSS[wid][lane * 4 + 2] = ss4.z; sSS[wid][lane * 4 + 3] = ss4.w;
    __syncthreads();
    if (threadIdx.x < DD) {
        float s = 0.f, ss = 0.f;
#pragma unroll
        for (int w = 0; w < 8; w++) { s += sS[w][threadIdx.x]; ss += sSS[w][threadIdx.x]; }
        g_partS [blockIdx.x * DD + threadIdx.x] = s;
        g_partSS[blockIdx.x * DD + threadIdx.x] = ss;
    }
}

// parallel finalize: 512 threads, 4 partial-sums per column
__global__ void k_bn_finalize(const float* __restrict__ gamma, const float* __restrict__ beta) {
    __shared__ float rS[4][DD], rSS[4][DD];
    int j = threadIdx.x & 127;
    int part = threadIdx.x >> 7;
    float s = 0.f, ss = 0.f;
    for (int bidx = part; bidx < NB_AGG; bidx += 4) {
        s  += g_partS [bidx * DD + j];
        ss += g_partSS[bidx * DD + j];
    }
    rS[part][j] = s; rSS[part][j] = ss;
    __syncthreads();
    if (part == 0) {
        s  = rS[0][j]  + rS[1][j]  + rS[2][j]  + rS[3][j];
        ss = rSS[0][j] + rSS[1][j] + rSS[2][j] + rSS[3][j];
        float mu  = s * (1.0f / NN);
        float var = ss * (1.0f / NN) - mu * mu;
        float scv = gamma[j] * rsqrtf(var + BN_EPS);
        g_bnp[j]      = scv;
        g_bnp[DD + j] = beta[j] - mu * scv;
    }
}

// ---------------- pooling (BN apply fused) + output ---------------------------
__global__ void k_pool(const int* __restrict__ batch) {
    int lane = threadIdx.x & 31;
    int node = (blockIdx.x * blockDim.x + threadIdx.x) >> 5;
    if (node >= NN) return;
    int g = batch[node];
    float4 v  = ((const float4*)g_h2)[(size_t)node * 32 + lane];
    float4 sc = ((const float4*)g_bnp)[lane];
    float4 sh = ((const float4*)g_bnp)[32 + lane];
    float hx = fmaxf(v.x * sc.x + sh.x, 0.f);
    float hy = fmaxf(v.y * sc.y + sh.y, 0.f);
    float hz = fmaxf(v.z * sc.z + sh.z, 0.f);
    float hw = fmaxf(v.w * sc.w + sh.w, 0.f);
    float* dst = g_pool + (size_t)g * 128 + lane * 4;
    asm volatile("red.global.add.v4.f32 [%0], {%1,%2,%3,%4};"
                 :: "l"(dst), "f"(hx), "f"(hy), "f"(hz), "f"(hw) : "memory");
    if (lane == 0) atomicAdd(&g_cnt[g], 1.0f);
}
__global__ void k_out(const float* __restrict__ Wout, const float* __restrict__ bout,
                      float* __restrict__ out) {
    int g = blockIdx.x, j = threadIdx.x;
    __shared__ float red[DD];
    float c  = fmaxf(g_cnt[g], 1.0f);
    float hg = g_pool[(size_t)g * 128 + j] / c;
#pragma unroll
    for (int t = 0; t < TT; t++) {
        red[j] = hg * Wout[j * TT + t];
        __syncthreads();
        for (int s = 64; s > 0; s >>= 1) {
            if (j < s) red[j] += red[j + s];
            __syncthreads();
        }
        if (j == 0) out[g * TT + t] = red[0] + bout[t];
        __syncthreads();
    }
}

// ---------------- host --------------------------------------------------------
extern "C" void kernel_launch(void* const* d_in, const int* in_sizes, int n_in,
                              void* d_out, int out_size) {
    const float* x     = (const float*)d_in[0];
    const int*   ei    = (const int*)  d_in[1];
    const int*   ea    = (const int*)  d_in[2];
    const int*   batch = (const int*)  d_in[3];
    const float* W     = (const float*)d_in[4];
    const float* b     = (const float*)d_in[5];
    const float* root  = (const float*)d_in[6];
    const float* bond  = (const float*)d_in[7];
    const float* gamma = (const float*)d_in[8];
    const float* beta  = (const float*)d_in[9];
    const float* Wout  = (const float*)d_in[10];
    const float* bout  = (const float*)d_in[11];
    float* out = (float*)d_out;

    const int* row = ei;
    const int* col = ei + EE;

    k_init<<<(NN + 255) / 256, 256>>>();
    k_count<<<(EE + 255) / 256, 256>>>(row, col);
    k_dinv<<<(NN + 255) / 256, 256>>>();
    k_scan1<<<NCHUNK, 1024>>>();
    k_scan2<<<1, 32>>>();
    k_scan3<<<(NN + 255) / 256, 256>>>();
    k_scatter<<<(EE + 255) / 256, 256>>>(row, col, ea);

    const int lin_blocks = (NN / 4 + 7) / 8;     // 4 rows/warp, 8 warps/block

    for (int l = 0; l < LL; l++) {
        const float* Wl = W     + (size_t)l * DD * DD;
        const float* bl = b     + (size_t)l * DD;
        const float* rl = root  + (size_t)l * DD;
        const float* el = bond  + (size_t)l * NBOND * DD;
        const float* gl = gamma + (size_t)l * DD;
        const float* tl = beta  + (size_t)l * DD;

        k_linear<<<lin_blocks, 256>>>(x, Wl, bl, l == 0 ? 0 : 1);
        k_agg<<<NB_AGG, 256>>>(el, rl);
        k_bn_finalize<<<1, 512>>>(gl, tl);
    }

    k_pool<<<(NN + 7) / 8, 256>>>(batch);
    k_out<<<GG, DD>>>(Wout, bout, out);
}

// round 12
// speedup vs baseline: 1.0730x; 1.0730x over previous
#include <cuda_runtime.h>
#include <cstdint>

#define NN 100000
#define EE 1600000
#define DD 128
#define LL 5
#define GG 128
#define TT 10
#define NBOND 4
#define BN_EPS 1e-5f
#define NB_AGG 592          // agg grid blocks (4/SM) — proven R4 config
#define NCHUNK 98           // ceil(NN/1024)

// ---------------- scratch (device globals) -----------------------------------
__device__ float g_hx [NN * DD];
__device__ float g_h2 [NN * DD];
__device__ float g_deg [NN];
__device__ float g_dinv[NN];
__device__ int   g_indeg[NN];
__device__ int   g_cur  [NN];
__device__ int   g_rowptr[NN + 1];
__device__ int   g_blocksum[NCHUNK];
__device__ int   g_blockoff[NCHUNK];
__device__ int   g_epack[EE];     // row | attr<<17, CSR order by dest
__device__ float g_enorm[EE];
__device__ float g_partS [NB_AGG * DD];
__device__ float g_partSS[NB_AGG * DD];
__device__ float g_bnp[2 * DD];   // scale / shift
__device__ float g_pool[GG * DD];
__device__ float g_cnt [GG];

// ---------------- prolog ------------------------------------------------------
__global__ void k_init() {
    int i = blockIdx.x * blockDim.x + threadIdx.x;
    if (i < NN) { g_deg[i] = 1.0f; g_indeg[i] = 0; g_cur[i] = 0; }
    if (i < GG * DD) g_pool[i] = 0.f;
    if (i < GG) g_cnt[i] = 0.f;
}
__global__ void k_count(const int* __restrict__ row, const int* __restrict__ col) {
    int e = blockIdx.x * blockDim.x + threadIdx.x;
    if (e < EE) {
        atomicAdd(&g_deg[row[e]], 1.0f);
        atomicAdd(&g_indeg[col[e]], 1);
    }
}
__global__ void k_dinv() {
    int i = blockIdx.x * blockDim.x + threadIdx.x;
    if (i < NN) g_dinv[i] = rsqrtf(g_deg[i]);
}
__global__ void k_scan1() {
    __shared__ int sm[1024];
    int tid = threadIdx.x;
    int i = blockIdx.x * 1024 + tid;
    int v = (i < NN) ? g_indeg[i] : 0;
    sm[tid] = v;
    __syncthreads();
    for (int off = 1; off < 1024; off <<= 1) {
        int t = (tid >= off) ? sm[tid - off] : 0;
        __syncthreads();
        sm[tid] += t;
        __syncthreads();
    }
    if (i < NN) g_rowptr[i] = sm[tid] - v;
    if (tid == 1023) g_blocksum[blockIdx.x] = sm[1023];
}
__global__ void k_scan2() {
    if (threadIdx.x == 0) {
        int run = 0;
        for (int bk = 0; bk < NCHUNK; bk++) { g_blockoff[bk] = run; run += g_blocksum[bk]; }
    }
}
__global__ void k_scan3() {
    int i = blockIdx.x * blockDim.x + threadIdx.x;
    if (i < NN) g_rowptr[i] += g_blockoff[i >> 10];
    if (i == 0) g_rowptr[NN] = EE;
}
__global__ void k_scatter(const int* __restrict__ row, const int* __restrict__ col,
                          const int* __restrict__ ea) {
    int e = blockIdx.x * blockDim.x + threadIdx.x;
    if (e >= EE) return;
    int r = row[e], c = col[e], a = ea[e];
    float nv = g_dinv[r] * g_dinv[c];
    int pos = g_rowptr[c] + atomicAdd(&g_cur[c], 1);
    g_epack[pos] = r | (a << 17);
    g_enorm[pos] = nv;
}

// ---------------- linear: hx = act(h) @ W + b  (4 rows/warp, R4-proven) -------
__global__ void k_linear(const float* __restrict__ h, const float* __restrict__ W,
                         const float* __restrict__ b, int use_bn) {
    int lane = threadIdx.x & 31;
    int gw   = (blockIdx.x * blockDim.x + threadIdx.x) >> 5;
    int r0   = gw * 4;
    if (r0 >= NN) return;
    const float4* h4 = use_bn ? (const float4*)g_h2 : (const float4*)h;
    const float4* W4 = (const float4*)W;
    float4 bv = ((const float4*)b)[lane];
    float4 sc, sh;
    if (use_bn) {
        sc = ((const float4*)g_bnp)[lane];
        sh = ((const float4*)g_bnp)[32 + lane];
    }
    float ha[4][4];
    float4 acc[4];
#pragma unroll
    for (int i = 0; i < 4; i++) {
        float4 t = h4[(size_t)(r0 + i) * 32 + lane];
        if (use_bn) {
            t.x = fmaxf(t.x * sc.x + sh.x, 0.f);
            t.y = fmaxf(t.y * sc.y + sh.y, 0.f);
            t.z = fmaxf(t.z * sc.z + sh.z, 0.f);
            t.w = fmaxf(t.w * sc.w + sh.w, 0.f);
        }
        ha[i][0] = t.x; ha[i][1] = t.y; ha[i][2] = t.z; ha[i][3] = t.w;
        acc[i] = bv;
    }
#pragma unroll 16
    for (int k = 0; k < 128; k++) {
        float4 w = W4[k * 32 + lane];
#pragma unroll
        for (int i = 0; i < 4; i++) {
            float hk = __shfl_sync(0xffffffffu, ha[i][k & 3], k >> 2);
            acc[i].x += hk * w.x; acc[i].y += hk * w.y;
            acc[i].z += hk * w.z; acc[i].w += hk * w.w;
        }
    }
#pragma unroll
    for (int i = 0; i < 4; i++)
        ((float4*)g_hx)[(size_t)(r0 + i) * 32 + lane] = acc[i];
}

// ---------------- fused aggregation: messages + self + BN partial stats -------
__global__ void __launch_bounds__(256) k_agg(const float* __restrict__ bond,
                                             const float* __restrict__ root) {
    __shared__ float sS [8][DD];
    __shared__ float sSS[8][DD];
    int lane = threadIdx.x & 31;
    int wid  = threadIdx.x >> 5;
    const float4* hx4 = (const float4*)g_hx;
    const float4* bd4 = (const float4*)bond;
    float4 rt = ((const float4*)root)[lane];
    float4 s4  = {0, 0, 0, 0};
    float4 ss4 = {0, 0, 0, 0};

    for (int c = blockIdx.x * 8 + wid; c < NN; c += NB_AGG * 8) {
        float4 acc = {0, 0, 0, 0};
        int e0 = g_rowptr[c], e1 = g_rowptr[c + 1];
        for (int e = e0; e < e1; e++) {
            int p = g_epack[e];
            float nv = g_enorm[e];
            int r = p & 0x1FFFF;
            int a = p >> 17;
            float4 hv = hx4[(size_t)r * 32 + lane];
            float4 bd = bd4[a * 32 + lane];
            acc.x += nv * fmaxf(hv.x + bd.x, 0.f);
            acc.y += nv * fmaxf(hv.y + bd.y, 0.f);
            acc.z += nv * fmaxf(hv.z + bd.z, 0.f);
            acc.w += nv * fmaxf(hv.w + bd.w, 0.f);
        }
        float4 hv = hx4[(size_t)c * 32 + lane];
        float inv = 1.0f / g_deg[c];
        acc.x += fmaxf(hv.x + rt.x, 0.f) * inv;
        acc.y += fmaxf(hv.y + rt.y, 0.f) * inv;
        acc.z += fmaxf(hv.z + rt.z, 0.f) * inv;
        acc.w += fmaxf(hv.w + rt.w, 0.f) * inv;
        ((float4*)g_h2)[(size_t)c * 32 + lane] = acc;
        s4.x += acc.x; s4.y += acc.y; s4.z += acc.z; s4.w += acc.w;
        ss4.x += acc.x * acc.x; ss4.y += acc.y * acc.y;
        ss4.z += acc.z * acc.z; ss4.w += acc.w * acc.w;
    }
    sS [wid][lane * 4 + 0] = s4.x;  sS [wid][lane * 4 + 1] = s4.y;
    sS [wid][lane * 4 + 2] = s4.z;  sS [wid][lane * 4 + 3] = s4.w;
    sSS[wid][lane * 4 + 0] = ss4.x; sSS[wid][lane * 4 + 1] = ss4.y;
    sSS[wid][lane * 4 + 2] = ss4.z; sSS[wid][lane * 4 + 3] = ss4.w;
    __syncthreads();
    if (threadIdx.x < DD) {
        float s = 0.f, ss = 0.f;
#pragma unroll
        for (int w = 0; w < 8; w++) { s += sS[w][threadIdx.x]; ss += sSS[w][threadIdx.x]; }
        g_partS [blockIdx.x * DD + threadIdx.x] = s;
        g_partSS[blockIdx.x * DD + threadIdx.x] = ss;
    }
}

// parallel finalize: 512 threads, 4 partial-sums per column
__global__ void k_bn_finalize(const float* __restrict__ gamma, const float* __restrict__ beta) {
    __shared__ float rS[4][DD], rSS[4][DD];
    int j = threadIdx.x & 127;
    int part = threadIdx.x >> 7;
    float s = 0.f, ss = 0.f;
    for (int bidx = part; bidx < NB_AGG; bidx += 4) {
        s  += g_partS [bidx * DD + j];
        ss += g_partSS[bidx * DD + j];
    }
    rS[part][j] = s; rSS[part][j] = ss;
    __syncthreads();
    if (part == 0) {
        s  = rS[0][j]  + rS[1][j]  + rS[2][j]  + rS[3][j];
        ss = rSS[0][j] + rSS[1][j] + rSS[2][j] + rSS[3][j];
        float mu  = s * (1.0f / NN);
        float var = ss * (1.0f / NN) - mu * mu;
        float scv = gamma[j] * rsqrtf(var + BN_EPS);
        g_bnp[j]      = scv;
        g_bnp[DD + j] = beta[j] - mu * scv;
    }
}

// ---------------- pooling (BN apply fused) + output ---------------------------
__global__ void k_pool(const int* __restrict__ batch) {
    int lane = threadIdx.x & 31;
    int node = (blockIdx.x * blockDim.x + threadIdx.x) >> 5;
    if (node >= NN) return;
    int g = batch[node];
    float4 v  = ((const float4*)g_h2)[(size_t)node * 32 + lane];
    float4 sc = ((const float4*)g_bnp)[lane];
    float4 sh = ((const float4*)g_bnp)[32 + lane];
    float hx = fmaxf(v.x * sc.x + sh.x, 0.f);
    float hy = fmaxf(v.y * sc.y + sh.y, 0.f);
    float hz = fmaxf(v.z * sc.z + sh.z, 0.f);
    float hw = fmaxf(v.w * sc.w + sh.w, 0.f);
    float* dst = g_pool + (size_t)g * 128 + lane * 4;
    asm volatile("red.global.add.v4.f32 [%0], {%1,%2,%3,%4};"
                 :: "l"(dst), "f"(hx), "f"(hy), "f"(hz), "f"(hw) : "memory");
    if (lane == 0) atomicAdd(&g_cnt[g], 1.0f);
}

// output GEMM: one warp per graph, shuffle reduction (no barriers)
__global__ void k_out(const float* __restrict__ Wout, const float* __restrict__ bout,
                      float* __restrict__ out) {
    int g    = blockIdx.x * (blockDim.x >> 5) + (threadIdx.x >> 5);
    int lane = threadIdx.x & 31;
    if (g >= GG) return;
    float c = fmaxf(g_cnt[g], 1.0f);
    float inv = 1.0f / c;
    // each lane owns 4 features: lane*4 .. lane*4+3
    float4 hg = ((const float4*)g_pool)[(size_t)g * 32 + lane];
    hg.x *= inv; hg.y *= inv; hg.z *= inv; hg.w *= inv;
#pragma unroll
    for (int t = 0; t < TT; t++) {
        float p = hg.x * Wout[(lane * 4 + 0) * TT + t]
                + hg.y * Wout[(lane * 4 + 1) * TT + t]
                + hg.z * Wout[(lane * 4 + 2) * TT + t]
                + hg.w * Wout[(lane * 4 + 3) * TT + t];
#pragma unroll
        for (int s = 16; s > 0; s >>= 1)
            p += __shfl_xor_sync(0xffffffffu, p, s);
        if (lane == 0) out[g * TT + t] = p + bout[t];
    }
}

// ---------------- host --------------------------------------------------------
extern "C" void kernel_launch(void* const* d_in, const int* in_sizes, int n_in,
                              void* d_out, int out_size) {
    const float* x     = (const float*)d_in[0];
    const int*   ei    = (const int*)  d_in[1];
    const int*   ea    = (const int*)  d_in[2];
    const int*   batch = (const int*)  d_in[3];
    const float* W     = (const float*)d_in[4];
    const float* b     = (const float*)d_in[5];
    const float* root  = (const float*)d_in[6];
    const float* bond  = (const float*)d_in[7];
    const float* gamma = (const float*)d_in[8];
    const float* beta  = (const float*)d_in[9];
    const float* Wout  = (const float*)d_in[10];
    const float* bout  = (const float*)d_in[11];
    float* out = (float*)d_out;

    const int* row = ei;
    const int* col = ei + EE;

    k_init<<<(NN + 255) / 256, 256>>>();
    k_count<<<(EE + 255) / 256, 256>>>(row, col);
    k_dinv<<<(NN + 255) / 256, 256>>>();
    k_scan1<<<NCHUNK, 1024>>>();
    k_scan2<<<1, 32>>>();
    k_scan3<<<(NN + 255) / 256, 256>>>();
    k_scatter<<<(EE + 255) / 256, 256>>>(row, col, ea);

    const int lin_blocks = (NN / 4 + 7) / 8;     // 4 rows/warp, 8 warps/block

    for (int l = 0; l < LL; l++) {
        const float* Wl = W     + (size_t)l * DD * DD;
        const float* bl = b     + (size_t)l * DD;
        const float* rl = root  + (size_t)l * DD;
        const float* el = bond  + (size_t)l * NBOND * DD;
        const float* gl = gamma + (size_t)l * DD;
        const float* tl = beta  + (size_t)l * DD;

        k_linear<<<lin_blocks, 256>>>(x, Wl, bl, l == 0 ? 0 : 1);
        k_agg<<<NB_AGG, 256>>>(el, rl);
        k_bn_finalize<<<1, 512>>>(gl, tl);
    }

    k_pool<<<(NN + 7) / 8, 256>>>(batch);
    k_out<<<(GG + 7) / 8, 256>>>(Wout, bout, out);
}

// round 14
// speedup vs baseline: 1.5650x; 1.4586x over previous
#include <cuda_runtime.h>
#include <cstdint>

#define NN 100000
#define EE 1600000
#define DD 128
#define LL 5
#define GG 128
#define TT 10
#define NBOND 4
#define BN_EPS 1e-5f
#define NB_AGG 592          // agg grid blocks (4/SM) — proven config
#define NCHUNK 98           // ceil(NN/1024)

// ---------------- scratch (device globals) -----------------------------------
__device__ float g_hx [NN * DD];
__device__ float g_h2 [NN * DD];
__device__ float g_deg [NN];
__device__ int   g_indeg[NN];
__device__ int   g_cur  [NN];
__device__ int   g_rowptr[NN + 1];
__device__ int   g_blocksum[NCHUNK];
__device__ int   g_blockoff[NCHUNK];
__device__ int2  g_edge[EE];      // {row | attr<<17, norm bits}, CSR order by dest
__device__ float g_partS [NB_AGG * DD];
__device__ float g_partSS[NB_AGG * DD];
__device__ float g_bnp[2 * DD];   // scale / shift
__device__ float g_pool[GG * DD];
__device__ float g_cnt [GG];

// ---------------- prolog ------------------------------------------------------
__global__ void k_init() {
    int i = blockIdx.x * blockDim.x + threadIdx.x;
    if (i < NN) { g_deg[i] = 1.0f; g_indeg[i] = 0; g_cur[i] = 0; }
    if (i < GG * DD) g_pool[i] = 0.f;
    if (i < GG) g_cnt[i] = 0.f;
}
__global__ void k_count(const int* __restrict__ row, const int* __restrict__ col) {
    int e = blockIdx.x * blockDim.x + threadIdx.x;
    if (e < EE) {
        atomicAdd(&g_deg[row[e]], 1.0f);
        atomicAdd(&g_indeg[col[e]], 1);
    }
}
__global__ void k_scan1() {
    __shared__ int sm[1024];
    int tid = threadIdx.x;
    int i = blockIdx.x * 1024 + tid;
    int v = (i < NN) ? g_indeg[i] : 0;
    sm[tid] = v;
    __syncthreads();
    for (int off = 1; off < 1024; off <<= 1) {
        int t = (tid >= off) ? sm[tid - off] : 0;
        __syncthreads();
        sm[tid] += t;
        __syncthreads();
    }
    if (i < NN) g_rowptr[i] = sm[tid] - v;
    if (tid == 1023) g_blocksum[blockIdx.x] = sm[1023];
}
__global__ void k_scan2() {
    if (threadIdx.x == 0) {
        int run = 0;
        for (int bk = 0; bk < NCHUNK; bk++) { g_blockoff[bk] = run; run += g_blocksum[bk]; }
    }
}
__global__ void k_scan3() {
    int i = blockIdx.x * blockDim.x + threadIdx.x;
    if (i < NN) g_rowptr[i] += g_blockoff[i >> 10];
    if (i == 0) g_rowptr[NN] = EE;
}
__global__ void k_scatter(const int* __restrict__ row, const int* __restrict__ col,
                          const int* __restrict__ ea) {
    int e = blockIdx.x * blockDim.x + threadIdx.x;
    if (e >= EE) return;
    int r = row[e], c = col[e], a = ea[e];
    float nv = rsqrtf(g_deg[r]) * rsqrtf(g_deg[c]);
    int pos = g_rowptr[c] + atomicAdd(&g_cur[c], 1);
    int2 rec;
    rec.x = r | (a << 17);
    rec.y = __float_as_int(nv);
    g_edge[pos] = rec;
}

// ---------------- linear: hx = act(h) @ W + b  (4 rows/warp, proven) ----------
__global__ void k_linear(const float* __restrict__ h, const float* __restrict__ W,
                         const float* __restrict__ b, int use_bn) {
    int lane = threadIdx.x & 31;
    int gw   = (blockIdx.x * blockDim.x + threadIdx.x) >> 5;
    int r0   = gw * 4;
    if (r0 >= NN) return;
    const float4* h4 = use_bn ? (const float4*)g_h2 : (const float4*)h;
    const float4* W4 = (const float4*)W;
    float4 bv = ((const float4*)b)[lane];
    float4 sc, sh;
    if (use_bn) {
        sc = ((const float4*)g_bnp)[lane];
        sh = ((const float4*)g_bnp)[32 + lane];
    }
    float ha[4][4];
    float4 acc[4];
#pragma unroll
    for (int i = 0; i < 4; i++) {
        float4 t = h4[(size_t)(r0 + i) * 32 + lane];
        if (use_bn) {
            t.x = fmaxf(t.x * sc.x + sh.x, 0.f);
            t.y = fmaxf(t.y * sc.y + sh.y, 0.f);
            t.z = fmaxf(t.z * sc.z + sh.z, 0.f);
            t.w = fmaxf(t.w * sc.w + sh.w, 0.f);
        }
        ha[i][0] = t.x; ha[i][1] = t.y; ha[i][2] = t.z; ha[i][3] = t.w;
        acc[i] = bv;
    }
#pragma unroll 16
    for (int k = 0; k < 128; k++) {
        float4 w = W4[k * 32 + lane];
#pragma unroll
        for (int i = 0; i < 4; i++) {
            float hk = __shfl_sync(0xffffffffu, ha[i][k & 3], k >> 2);
            acc[i].x += hk * w.x; acc[i].y += hk * w.y;
            acc[i].z += hk * w.z; acc[i].w += hk * w.w;
        }
    }
#pragma unroll
    for (int i = 0; i < 4; i++)
        ((float4*)g_hx)[(size_t)(r0 + i) * 32 + lane] = acc[i];
}

// ---------------- fused aggregation: messages + self + BN partial stats -------
__global__ void __launch_bounds__(256) k_agg(const float* __restrict__ bond,
                                             const float* __restrict__ root) {
    __shared__ float sS [8][DD];
    __shared__ float sSS[8][DD];
    int lane = threadIdx.x & 31;
    int wid  = threadIdx.x >> 5;
    const float4* hx4 = (const float4*)g_hx;
    const float4* bd4 = (const float4*)bond;
    float4 rt = ((const float4*)root)[lane];
    float4 s4  = {0, 0, 0, 0};
    float4 ss4 = {0, 0, 0, 0};

    for (int c = blockIdx.x * 8 + wid; c < NN; c += NB_AGG * 8) {
        float4 acc = {0, 0, 0, 0};
        int e0 = g_rowptr[c], e1 = g_rowptr[c + 1];
        for (int e = e0; e < e1; e++) {
            int2 rec = g_edge[e];
            float nv = __int_as_float(rec.y);
            int r = rec.x & 0x1FFFF;
            int a = rec.x >> 17;
            float4 hv = hx4[(size_t)r * 32 + lane];
            float4 bd = bd4[a * 32 + lane];
            acc.x += nv * fmaxf(hv.x + bd.x, 0.f);
            acc.y += nv * fmaxf(hv.y + bd.y, 0.f);
            acc.z += nv * fmaxf(hv.z + bd.z, 0.f);
            acc.w += nv * fmaxf(hv.w + bd.w, 0.f);
        }
        float4 hv = hx4[(size_t)c * 32 + lane];
        float inv = 1.0f / g_deg[c];
        acc.x += fmaxf(hv.x + rt.x, 0.f) * inv;
        acc.y += fmaxf(hv.y + rt.y, 0.f) * inv;
        acc.z += fmaxf(hv.z + rt.z, 0.f) * inv;
        acc.w += fmaxf(hv.w + rt.w, 0.f) * inv;
        ((float4*)g_h2)[(size_t)c * 32 + lane] = acc;
        s4.x += acc.x; s4.y += acc.y; s4.z += acc.z; s4.w += acc.w;
        ss4.x += acc.x * acc.x; ss4.y += acc.y * acc.y;
        ss4.z += acc.z * acc.z; ss4.w += acc.w * acc.w;
    }
    sS [wid][lane * 4 + 0] = s4.x;  sS [wid][lane * 4 + 1] = s4.y;
    sS [wid][lane * 4 + 2] = s4.z;  sS [wid][lane * 4 + 3] = s4.w;
    sSS[wid][lane * 4 + 0] = ss4.x; sSS[wid][lane * 4 + 1] = ss4.y;
    sSS[wid][lane * 4 + 2] = ss4.z; sSS[wid][lane * 4 + 3] = ss4.w;
    __syncthreads();
    if (threadIdx.x < DD) {
        float s = 0.f, ss = 0.f;
#pragma unroll
        for (int w = 0; w < 8; w++) { s += sS[w][threadIdx.x]; ss += sSS[w][threadIdx.x]; }
        g_partS [blockIdx.x * DD + threadIdx.x] = s;
        g_partSS[blockIdx.x * DD + threadIdx.x] = ss;
    }
}

// parallel finalize: 512 threads, 4 partial-sums per column
__global__ void k_bn_finalize(const float* __restrict__ gamma, const float* __restrict__ beta) {
    __shared__ float rS[4][DD], rSS[4][DD];
    int j = threadIdx.x & 127;
    int part = threadIdx.x >> 7;
    float s = 0.f, ss = 0.f;
    for (int bidx = part; bidx < NB_AGG; bidx += 4) {
        s  += g_partS [bidx * DD + j];
        ss += g_partSS[bidx * DD + j];
    }
    rS[part][j] = s; rSS[part][j] = ss;
    __syncthreads();
    if (part == 0) {
        s  = rS[0][j]  + rS[1][j]  + rS[2][j]  + rS[3][j];
        ss = rSS[0][j] + rSS[1][j] + rSS[2][j] + rSS[3][j];
        float mu  = s * (1.0f / NN);
        float var = ss * (1.0f / NN) - mu * mu;
        float scv = gamma[j] * rsqrtf(var + BN_EPS);
        g_bnp[j]      = scv;
        g_bnp[DD + j] = beta[j] - mu * scv;
    }
}

// ---------------- pooling (BN apply fused) + output ---------------------------
__global__ void k_pool(const int* __restrict__ batch) {
    int lane = threadIdx.x & 31;
    int node = (blockIdx.x * blockDim.x + threadIdx.x) >> 5;
    if (node >= NN) return;
    int g = batch[node];
    float4 v  = ((const float4*)g_h2)[(size_t)node * 32 + lane];
    float4 sc = ((const float4*)g_bnp)[lane];
    float4 sh = ((const float4*)g_bnp)[32 + lane];
    float hx = fmaxf(v.x * sc.x + sh.x, 0.f);
    float hy = fmaxf(v.y * sc.y + sh.y, 0.f);
    float hz = fmaxf(v.z * sc.z + sh.z, 0.f);
    float hw = fmaxf(v.w * sc.w + sh.w, 0.f);
    float* dst = g_pool + (size_t)g * 128 + lane * 4;
    asm volatile("red.global.add.v4.f32 [%0], {%1,%2,%3,%4};"
                 :: "l"(dst), "f"(hx), "f"(hy), "f"(hz), "f"(hw) : "memory");
    if (lane == 0) atomicAdd(&g_cnt[g], 1.0f);
}

// output GEMM: one warp per graph, shuffle reduction
__global__ void k_out(const float* __restrict__ Wout, const float* __restrict__ bout,
                      float* __restrict__ out) {
    int g    = blockIdx.x * (blockDim.x >> 5) + (threadIdx.x >> 5);
    int lane = threadIdx.x & 31;
    if (g >= GG) return;
    float c = fmaxf(g_cnt[g], 1.0f);
    float inv = 1.0f / c;
    float4 hg = ((const float4*)g_pool)[(size_t)g * 32 + lane];
    hg.x *= inv; hg.y *= inv; hg.z *= inv; hg.w *= inv;
#pragma unroll
    for (int t = 0; t < TT; t++) {
        float p = hg.x * Wout[(lane * 4 + 0) * TT + t]
                + hg.y * Wout[(lane * 4 + 1) * TT + t]
                + hg.z * Wout[(lane * 4 + 2) * TT + t]
                + hg.w * Wout[(lane * 4 + 3) * TT + t];
#pragma unroll
        for (int s = 16; s > 0; s >>= 1)
            p += __shfl_xor_sync(0xffffffffu, p, s);
        if (lane == 0) out[g * TT + t] = p + bout[t];
    }
}

// ---------------- host --------------------------------------------------------
extern "C" void kernel_launch(void* const* d_in, const int* in_sizes, int n_in,
                              void* d_out, int out_size) {
    const float* x     = (const float*)d_in[0];
    const int*   ei    = (const int*)  d_in[1];
    const int*   ea    = (const int*)  d_in[2];
    const int*   batch = (const int*)  d_in[3];
    const float* W     = (const float*)d_in[4];
    const float* b     = (const float*)d_in[5];
    const float* root  = (const float*)d_in[6];
    const float* bond  = (const float*)d_in[7];
    const float* gamma = (const float*)d_in[8];
    const float* beta  = (const float*)d_in[9];
    const float* Wout  = (const float*)d_in[10];
    const float* bout  = (const float*)d_in[11];
    float* out = (float*)d_out;

    const int* row = ei;
    const int* col = ei + EE;

    k_init<<<(NN + 255) / 256, 256>>>();
    k_count<<<(EE + 255) / 256, 256>>>(row, col);
    k_scan1<<<NCHUNK, 1024>>>();
    k_scan2<<<1, 32>>>();
    k_scan3<<<(NN + 255) / 256, 256>>>();
    k_scatter<<<(EE + 255) / 256, 256>>>(row, col, ea);

    const int lin_blocks = (NN / 4 + 7) / 8;     // 4 rows/warp, 8 warps/block

    for (int l = 0; l < LL; l++) {
        const float* Wl = W     + (size_t)l * DD * DD;
        const float* bl = b     + (size_t)l * DD;
        const float* rl = root  + (size_t)l * DD;
        const float* el = bond  + (size_t)l * NBOND * DD;
        const float* gl = gamma + (size_t)l * DD;
        const float* tl = beta  + (size_t)l * DD;

        k_linear<<<lin_blocks, 256>>>(x, Wl, bl, l == 0 ? 0 : 1);
        k_agg<<<NB_AGG, 256>>>(el, rl);
        k_bn_finalize<<<1, 512>>>(gl, tl);
    }

    k_pool<<<(NN + 7) / 8, 256>>>(batch);
    k_out<<<(GG + 7) / 8, 256>>>(Wout, bout, out);
}